// round 2
// baseline (speedup 1.0000x reference)
#include <cuda_runtime.h>

#define D      768
#define LSEQ   528
#define BSZ    64
#define NHEADS 12
#define DH     64
#define MTOT   (BSZ * LSEQ)           // 33792
#define SCALE  0.03608439182435161f   // 768^-0.5

// Scratch (allocation-free rule: __device__ globals)
__device__ float g_q[(size_t)MTOT * D];
__device__ float g_k[(size_t)MTOT * D];
__device__ float g_v[(size_t)MTOT * D];
__device__ float g_att[(size_t)MTOT * D];

// ---------------------------------------------------------------------------
// Tiled fp32 GEMM body: C[M,768] = A[M,768] @ W[768,768] (+bias)
// 64x64 tile, BK=16, 256 threads, 4x4 micro-tile.
// ---------------------------------------------------------------------------
__device__ __forceinline__ void gemm_body(const float* __restrict__ A,
                                          const float* __restrict__ W,
                                          float* __restrict__ C,
                                          const float* __restrict__ bias)
{
    __shared__ float As[16][64];   // transposed: As[k][m]
    __shared__ float Bs[16][64];   // Bs[k][n]

    const int tid = threadIdx.x;
    const int m0 = blockIdx.y << 6;
    const int n0 = blockIdx.x << 6;
    const int ty = tid >> 4, tx = tid & 15;

    const int a_row = tid >> 2;          // 0..63
    const int a_col = (tid & 3) << 2;    // 0,4,8,12
    const int b_row = tid >> 4;          // 0..15
    const int b_col = (tid & 15) << 2;   // 0..60

    const float* Ap = A + (size_t)(m0 + a_row) * D + a_col;
    const float* Wp = W + (size_t)b_row * D + n0 + b_col;

    float acc[4][4] = {};

    for (int k0 = 0; k0 < D; k0 += 16) {
        float4 av = *(const float4*)(Ap + k0);
        As[a_col + 0][a_row] = av.x;
        As[a_col + 1][a_row] = av.y;
        As[a_col + 2][a_row] = av.z;
        As[a_col + 3][a_row] = av.w;
        *(float4*)&Bs[b_row][b_col] = *(const float4*)(Wp + (size_t)k0 * D);
        __syncthreads();
#pragma unroll
        for (int k = 0; k < 16; ++k) {
            float4 a = *(const float4*)&As[k][ty << 2];
            float4 b = *(const float4*)&Bs[k][tx << 2];
            float ar[4] = {a.x, a.y, a.z, a.w};
            float br[4] = {b.x, b.y, b.z, b.w};
#pragma unroll
            for (int i = 0; i < 4; ++i)
#pragma unroll
                for (int j = 0; j < 4; ++j) acc[i][j] += ar[i] * br[j];
        }
        __syncthreads();
    }

    float4 bb = make_float4(0.f, 0.f, 0.f, 0.f);
    if (bias) bb = *(const float4*)(bias + n0 + (tx << 2));
#pragma unroll
    for (int i = 0; i < 4; ++i) {
        float4 r;
        r.x = acc[i][0] + bb.x;
        r.y = acc[i][1] + bb.y;
        r.z = acc[i][2] + bb.z;
        r.w = acc[i][3] + bb.w;
        *(float4*)(C + (size_t)(m0 + (ty << 2) + i) * D + n0 + (tx << 2)) = r;
    }
}

__global__ void __launch_bounds__(256) qkv_kernel(const float* __restrict__ x,
                                                  const float* __restrict__ Wq,
                                                  const float* __restrict__ Wk,
                                                  const float* __restrict__ Wv)
{
    const float* W;
    float* C;
    if (blockIdx.z == 0)      { W = Wq; C = g_q; }
    else if (blockIdx.z == 1) { W = Wk; C = g_k; }
    else                      { W = Wv; C = g_v; }
    gemm_body(x, W, C, nullptr);
}

__global__ void __launch_bounds__(256) proj_kernel(const float* __restrict__ Wp,
                                                   const float* __restrict__ bias,
                                                   float* __restrict__ out)
{
    gemm_body(g_att, Wp, out, bias);
}

// ---------------------------------------------------------------------------
// Attention: one block per (q-tile of 64, head, batch). Online softmax.
// Queries < 128 attend keys [0,128); queries >= 128 attend keys [0,528).
// Smem: Qt (transposed), KtP (K transposed, later reused for P with XOR
// swizzle keeping scalar reads conflict-free), Vs (row-major). 48KB exactly.
// ---------------------------------------------------------------------------
__global__ void __launch_bounds__(256) attn_kernel()
{
    __shared__ float Qt[64 * 64];
    __shared__ float KtP[64 * 64];
    __shared__ float Vs[64 * 64];

    const int qt = blockIdx.x, h = blockIdx.y, b = blockIdx.z;
    const int q0 = qt << 6;
    const int nq = min(64, LSEQ - q0);
    const int nk = (q0 < 128) ? 128 : LSEQ;
    const int tid = threadIdx.x;
    const int ty = tid >> 4, tx = tid & 15;
    const size_t base = (size_t)b * LSEQ * D + (size_t)h * DH;

    // Load Q tile transposed: Qt[d][r]. Warp covers 32 consecutive r -> STS conflict-free.
#pragma unroll
    for (int it = 0; it < 4; ++it) {
        int idx = tid + (it << 8);
        int r = idx & 63;
        int c = (idx >> 6) << 2;
        float4 v = make_float4(0.f, 0.f, 0.f, 0.f);
        if (r < nq) v = *(const float4*)(g_q + base + (size_t)(q0 + r) * D + c);
        Qt[(c + 0) * 64 + r] = v.x;
        Qt[(c + 1) * 64 + r] = v.y;
        Qt[(c + 2) * 64 + r] = v.z;
        Qt[(c + 3) * 64 + r] = v.w;
    }

    float oacc[4][4] = {};
    float row_max[4] = {-1e30f, -1e30f, -1e30f, -1e30f};
    float row_sum[4] = {0.f, 0.f, 0.f, 0.f};

    for (int k0 = 0; k0 < nk; k0 += 64) {
        const int nkv = min(64, nk - k0);
        __syncthreads();  // prior-iter PV reads done (and Qt stores on iter 0)

        // Load K tile transposed + V tile row-major (zero-padded)
#pragma unroll
        for (int it = 0; it < 4; ++it) {
            int idx = tid + (it << 8);
            int r = idx & 63;
            int c = (idx >> 6) << 2;
            float4 kv = make_float4(0.f, 0.f, 0.f, 0.f);
            if (r < nkv) kv = *(const float4*)(g_k + base + (size_t)(k0 + r) * D + c);
            KtP[(c + 0) * 64 + r] = kv.x;
            KtP[(c + 1) * 64 + r] = kv.y;
            KtP[(c + 2) * 64 + r] = kv.z;
            KtP[(c + 3) * 64 + r] = kv.w;
            int r2 = idx >> 4;
            int c2 = (idx & 15) << 2;
            float4 vv = make_float4(0.f, 0.f, 0.f, 0.f);
            if (r2 < nkv) vv = *(const float4*)(g_v + base + (size_t)(k0 + r2) * D + c2);
            *(float4*)&Vs[r2 * 64 + c2] = vv;
        }
        __syncthreads();

        // S = Q K^T (this thread: rows 4ty..+3, cols 4tx..+3)
        float s[4][4] = {};
#pragma unroll 16
        for (int d = 0; d < 64; ++d) {
            float4 qv = *(const float4*)&Qt[d * 64 + (ty << 2)];
            float4 kv = *(const float4*)&KtP[d * 64 + (tx << 2)];
            float qr[4] = {qv.x, qv.y, qv.z, qv.w};
            float kr[4] = {kv.x, kv.y, kv.z, kv.w};
#pragma unroll
            for (int i = 0; i < 4; ++i)
#pragma unroll
                for (int j = 0; j < 4; ++j) s[i][j] += qr[i] * kr[j];
        }
#pragma unroll
        for (int i = 0; i < 4; ++i)
#pragma unroll
            for (int j = 0; j < 4; ++j) {
                float sv = s[i][j] * SCALE;
                if (k0 + (tx << 2) + j >= nk) sv = -1e30f;
                s[i][j] = sv;
            }
        __syncthreads();  // everyone done reading KtP as K before P overwrite

        // Online softmax per row; write P into KtP (swizzled)
#pragma unroll
        for (int i = 0; i < 4; ++i) {
            float m = fmaxf(fmaxf(s[i][0], s[i][1]), fmaxf(s[i][2], s[i][3]));
            m = fmaxf(m, __shfl_xor_sync(0xffffffffu, m, 8, 16));
            m = fmaxf(m, __shfl_xor_sync(0xffffffffu, m, 4, 16));
            m = fmaxf(m, __shfl_xor_sync(0xffffffffu, m, 2, 16));
            m = fmaxf(m, __shfl_xor_sync(0xffffffffu, m, 1, 16));
            float nm = fmaxf(row_max[i], m);
            float corr = __expf(row_max[i] - nm);
            row_max[i] = nm;
            row_sum[i] *= corr;
#pragma unroll
            for (int j = 0; j < 4; ++j) oacc[i][j] *= corr;
            const int R = (ty << 2) + i;
            const int sw = (R & 7) << 2;
            float ps = 0.f;
#pragma unroll
            for (int j = 0; j < 4; ++j) {
                float p = __expf(s[i][j] - nm);
                ps += p;
                KtP[R * 64 + (((tx << 2) + j) ^ sw)] = p;
            }
            ps += __shfl_xor_sync(0xffffffffu, ps, 8, 16);
            ps += __shfl_xor_sync(0xffffffffu, ps, 4, 16);
            ps += __shfl_xor_sync(0xffffffffu, ps, 2, 16);
            ps += __shfl_xor_sync(0xffffffffu, ps, 1, 16);
            row_sum[i] += ps;
        }
        __syncthreads();

        // O += P @ V
#pragma unroll 8
        for (int j = 0; j < 64; ++j) {
            float4 vv = *(const float4*)&Vs[j * 64 + (tx << 2)];
            float vr[4] = {vv.x, vv.y, vv.z, vv.w};
#pragma unroll
            for (int i = 0; i < 4; ++i) {
                const int R = (ty << 2) + i;
                float p = KtP[R * 64 + (j ^ ((R & 7) << 2))];
#pragma unroll
                for (int jj = 0; jj < 4; ++jj) oacc[i][jj] += p * vr[jj];
            }
        }
    }

    // Normalize and store
#pragma unroll
    for (int i = 0; i < 4; ++i) {
        const int r = (ty << 2) + i;
        if (r < nq) {
            float inv = 1.f / row_sum[i];
            float4 ov = make_float4(oacc[i][0] * inv, oacc[i][1] * inv,
                                    oacc[i][2] * inv, oacc[i][3] * inv);
            *(float4*)(g_att + base + (size_t)(q0 + r) * D + (tx << 2)) = ov;
        }
    }
}

// ---------------------------------------------------------------------------
extern "C" void kernel_launch(void* const* d_in, const int* in_sizes, int n_in,
                              void* d_out, int out_size)
{
    const float* x   = (const float*)d_in[0];
    const float* Wq  = (const float*)d_in[1];
    const float* Wk  = (const float*)d_in[2];
    const float* Wv  = (const float*)d_in[3];
    const float* Wp  = (const float*)d_in[4];
    const float* bp  = (const float*)d_in[5];
    float* out = (float*)d_out;

    dim3 gq(D / 64, MTOT / 64, 3);           // (12, 528, 3)
    qkv_kernel<<<gq, 256>>>(x, Wq, Wk, Wv);

    dim3 ga((LSEQ + 63) / 64, NHEADS, BSZ);  // (9, 12, 64)
    attn_kernel<<<ga, 256>>>();

    dim3 gp(D / 64, MTOT / 64, 1);           // (12, 528)
    proj_kernel<<<gp, 256>>>(Wp, bp, out);
}

// round 3
// speedup vs baseline: 2.6198x; 2.6198x over previous
#include <cuda_runtime.h>
#include <cstdint>

#define D      768
#define LSEQ   528
#define BSZ    64
#define NHEADS 12
#define DH     64
#define MTOT   (BSZ * LSEQ)           // 33792
#define SCALE  0.03608439182435161f   // 768^-0.5

// Scratch (allocation-free rule: __device__ globals)
__device__ float g_q[(size_t)MTOT * D];
__device__ float g_k[(size_t)MTOT * D];
__device__ float g_v[(size_t)MTOT * D];
__device__ float g_att[(size_t)MTOT * D];

__device__ __forceinline__ uint32_t f2tf32(float f) {
    uint32_t u;
    asm("cvt.rna.tf32.f32 %0, %1;" : "=r"(u) : "f"(f));
    return u;
}

__device__ __forceinline__ void mma_tf32(float c[4], uint32_t a0, uint32_t a1,
                                         uint32_t a2, uint32_t a3,
                                         uint32_t b0, uint32_t b1) {
    asm volatile(
        "mma.sync.aligned.m16n8k8.row.col.f32.tf32.tf32.f32 "
        "{%0,%1,%2,%3}, {%4,%5,%6,%7}, {%8,%9}, {%0,%1,%2,%3};"
        : "+f"(c[0]), "+f"(c[1]), "+f"(c[2]), "+f"(c[3])
        : "r"(a0), "r"(a1), "r"(a2), "r"(a3), "r"(b0), "r"(b1));
}

// ---------------------------------------------------------------------------
// tf32 tensor-core GEMM: C[M,768] = A[M,768] @ W[768,768] (+bias)
// 128x128 tile, BK=16, 256 threads (8 warps, 2x4), warp tile 64x32.
// ---------------------------------------------------------------------------
#define BM 128
#define BN 128
#define BK 16
#define AS_STRIDE 132
#define BS_STRIDE 132

__device__ __forceinline__ void gemm_body(const float* __restrict__ A,
                                          const float* __restrict__ W,
                                          float* __restrict__ C,
                                          const float* __restrict__ bias)
{
    __shared__ uint32_t As[BK * AS_STRIDE];   // As[k][m]
    __shared__ uint32_t Bs[BK * BS_STRIDE];   // Bs[k][n]

    const int tid = threadIdx.x;
    const int m0 = blockIdx.y * BM;
    const int n0 = blockIdx.x * BN;

    const int lane = tid & 31;
    const int warp = tid >> 5;
    const int g  = lane >> 2;     // groupID 0..7
    const int tg = lane & 3;      // thread-in-group 0..3
    const int wr = warp >> 2;     // 0..1  -> M offset 64*wr
    const int wc = warp & 3;      // 0..3  -> N offset 32*wc
    const int mb = wr * 64;
    const int nb = wc * 32;

    // global loaders
    const int ar = tid >> 2;          // 0..63 (and +64)
    const int ac = (tid & 3) << 2;    // 0,4,8,12
    const int bkr = tid >> 5;         // 0..7 (and +8)
    const int bc = (lane) << 2;       // 0..124

    const float* Ap0 = A + (size_t)(m0 + ar) * D + ac;
    const float* Ap1 = A + (size_t)(m0 + ar + 64) * D + ac;
    const float* Wp0 = W + (size_t)bkr * D + n0 + bc;
    const float* Wp1 = W + (size_t)(bkr + 8) * D + n0 + bc;

    float acc[4][4][4] = {};

    float4 pa0 = *(const float4*)(Ap0);
    float4 pa1 = *(const float4*)(Ap1);
    float4 pb0 = *(const float4*)(Wp0);
    float4 pb1 = *(const float4*)(Wp1);

    for (int kt = 0; kt < D / BK; ++kt) {
        // store current tile to smem (tf32-converted)
        As[(ac + 0) * AS_STRIDE + ar] = f2tf32(pa0.x);
        As[(ac + 1) * AS_STRIDE + ar] = f2tf32(pa0.y);
        As[(ac + 2) * AS_STRIDE + ar] = f2tf32(pa0.z);
        As[(ac + 3) * AS_STRIDE + ar] = f2tf32(pa0.w);
        As[(ac + 0) * AS_STRIDE + ar + 64] = f2tf32(pa1.x);
        As[(ac + 1) * AS_STRIDE + ar + 64] = f2tf32(pa1.y);
        As[(ac + 2) * AS_STRIDE + ar + 64] = f2tf32(pa1.z);
        As[(ac + 3) * AS_STRIDE + ar + 64] = f2tf32(pa1.w);
        {
            uint4 u0 = make_uint4(f2tf32(pb0.x), f2tf32(pb0.y), f2tf32(pb0.z), f2tf32(pb0.w));
            uint4 u1 = make_uint4(f2tf32(pb1.x), f2tf32(pb1.y), f2tf32(pb1.z), f2tf32(pb1.w));
            *(uint4*)&Bs[bkr * BS_STRIDE + bc] = u0;
            *(uint4*)&Bs[(bkr + 8) * BS_STRIDE + bc] = u1;
        }
        __syncthreads();

        if (kt + 1 < D / BK) {
            const int k0 = (kt + 1) * BK;
            pa0 = *(const float4*)(Ap0 + k0);
            pa1 = *(const float4*)(Ap1 + k0);
            pb0 = *(const float4*)(Wp0 + (size_t)k0 * D);
            pb1 = *(const float4*)(Wp1 + (size_t)k0 * D);
        }

#pragma unroll
        for (int kk = 0; kk < BK; kk += 8) {
            uint32_t afr[4][4];
#pragma unroll
            for (int i = 0; i < 4; ++i) {
                afr[i][0] = As[(kk + tg) * AS_STRIDE + mb + i * 16 + g];
                afr[i][1] = As[(kk + tg) * AS_STRIDE + mb + i * 16 + g + 8];
                afr[i][2] = As[(kk + tg + 4) * AS_STRIDE + mb + i * 16 + g];
                afr[i][3] = As[(kk + tg + 4) * AS_STRIDE + mb + i * 16 + g + 8];
            }
#pragma unroll
            for (int j = 0; j < 4; ++j) {
                uint32_t b0 = Bs[(kk + tg) * BS_STRIDE + nb + j * 8 + g];
                uint32_t b1 = Bs[(kk + tg + 4) * BS_STRIDE + nb + j * 8 + g];
#pragma unroll
                for (int i = 0; i < 4; ++i)
                    mma_tf32(acc[i][j], afr[i][0], afr[i][1], afr[i][2], afr[i][3], b0, b1);
            }
        }
        __syncthreads();
    }

    // epilogue
#pragma unroll
    for (int j = 0; j < 4; ++j) {
        const int cn = n0 + nb + j * 8 + 2 * tg;
        float b0 = 0.f, b1 = 0.f;
        if (bias) { b0 = bias[cn]; b1 = bias[cn + 1]; }
#pragma unroll
        for (int i = 0; i < 4; ++i) {
            const int rm = m0 + mb + i * 16 + g;
            float2 v0 = make_float2(acc[i][j][0] + b0, acc[i][j][1] + b1);
            float2 v1 = make_float2(acc[i][j][2] + b0, acc[i][j][3] + b1);
            *(float2*)(C + (size_t)rm * D + cn) = v0;
            *(float2*)(C + (size_t)(rm + 8) * D + cn) = v1;
        }
    }
}

__global__ void __launch_bounds__(256) qkv_kernel(const float* __restrict__ x,
                                                  const float* __restrict__ Wq,
                                                  const float* __restrict__ Wk,
                                                  const float* __restrict__ Wv)
{
    const float* W;
    float* C;
    if (blockIdx.z == 0)      { W = Wq; C = g_q; }
    else if (blockIdx.z == 1) { W = Wk; C = g_k; }
    else                      { W = Wv; C = g_v; }
    gemm_body(x, W, C, nullptr);
}

__global__ void __launch_bounds__(256) proj_kernel(const float* __restrict__ Wp,
                                                   const float* __restrict__ bias,
                                                   float* __restrict__ out)
{
    gemm_body(g_att, Wp, out, bias);
}

// ---------------------------------------------------------------------------
// tf32 tensor-core flash attention.
// 1 block = 64 queries x 1 head x 1 batch. 128 threads = 4 warps;
// warp w owns query rows [16w, 16w+16), full 64-key tile => warp-local softmax.
// Dynamic smem (52224B): Qt[d][q], Ks[d][key] (reused as Ps[q][key]), Vs[key][d].
// ---------------------------------------------------------------------------
#define AT_STRIDE 68
#define SM_QT 0
#define SM_KS (64 * AT_STRIDE)
#define SM_VS (2 * 64 * AT_STRIDE)
#define SMEM_ATTN (3 * 64 * AT_STRIDE * 4)

__global__ void __launch_bounds__(128) attn_kernel()
{
    extern __shared__ uint32_t sm[];
    uint32_t* Qt = sm + SM_QT;
    uint32_t* Ks = sm + SM_KS;   // aliased as Ps after S phase
    uint32_t* Vs = sm + SM_VS;

    const int qt = blockIdx.x, h = blockIdx.y, b = blockIdx.z;
    const int q0 = qt << 6;
    const int nq = min(64, LSEQ - q0);
    const int nk = (q0 < 128) ? 128 : LSEQ;
    const int tid = threadIdx.x;
    const int lane = tid & 31;
    const int warp = tid >> 5;      // 0..3
    const int g  = lane >> 2;
    const int tg = lane & 3;
    const int mrow = warp * 16;
    const size_t base = (size_t)b * LSEQ * D + (size_t)h * DH;

    // Load Q transposed (tf32): Qt[d][q]
#pragma unroll
    for (int it = 0; it < 8; ++it) {
        int idx = tid + (it << 7);
        int r = idx & 63;
        int c4 = (idx >> 6) << 2;
        float4 v = make_float4(0.f, 0.f, 0.f, 0.f);
        if (r < nq) v = *(const float4*)(g_q + base + (size_t)(q0 + r) * D + c4);
        Qt[(c4 + 0) * AT_STRIDE + r] = f2tf32(v.x);
        Qt[(c4 + 1) * AT_STRIDE + r] = f2tf32(v.y);
        Qt[(c4 + 2) * AT_STRIDE + r] = f2tf32(v.z);
        Qt[(c4 + 3) * AT_STRIDE + r] = f2tf32(v.w);
    }

    float o[8][4] = {};
    float row_max[2] = {-1e30f, -1e30f};
    float row_sum[2] = {0.f, 0.f};

    for (int kt0 = 0; kt0 < nk; kt0 += 64) {
        const int nkv = min(64, nk - kt0);
        __syncthreads();   // prev PV reads / initial Qt stores done

        // Load K transposed + V row-major (tf32, zero-padded)
#pragma unroll
        for (int it = 0; it < 8; ++it) {
            int idx = tid + (it << 7);
            int r = idx & 63;
            int c4 = (idx >> 6) << 2;
            float4 kv = make_float4(0.f, 0.f, 0.f, 0.f);
            if (r < nkv) kv = *(const float4*)(g_k + base + (size_t)(kt0 + r) * D + c4);
            Ks[(c4 + 0) * AT_STRIDE + r] = f2tf32(kv.x);
            Ks[(c4 + 1) * AT_STRIDE + r] = f2tf32(kv.y);
            Ks[(c4 + 2) * AT_STRIDE + r] = f2tf32(kv.z);
            Ks[(c4 + 3) * AT_STRIDE + r] = f2tf32(kv.w);
            int r2 = idx >> 4;
            int c2 = (idx & 15) << 2;
            float4 vv = make_float4(0.f, 0.f, 0.f, 0.f);
            if (r2 < nkv) vv = *(const float4*)(g_v + base + (size_t)(kt0 + r2) * D + c2);
            uint4 u = make_uint4(f2tf32(vv.x), f2tf32(vv.y), f2tf32(vv.z), f2tf32(vv.w));
            *(uint4*)&Vs[r2 * AT_STRIDE + c2] = u;
        }
        __syncthreads();

        // S = Q K^T : warp computes rows [mrow, mrow+16) x 64 keys
        float s[8][4] = {};
#pragma unroll
        for (int kk = 0; kk < 64; kk += 8) {
            uint32_t a0 = Qt[(kk + tg) * AT_STRIDE + mrow + g];
            uint32_t a1 = Qt[(kk + tg) * AT_STRIDE + mrow + g + 8];
            uint32_t a2 = Qt[(kk + tg + 4) * AT_STRIDE + mrow + g];
            uint32_t a3 = Qt[(kk + tg + 4) * AT_STRIDE + mrow + g + 8];
#pragma unroll
            for (int j = 0; j < 8; ++j) {
                uint32_t b0 = Ks[(kk + tg) * AT_STRIDE + j * 8 + g];
                uint32_t b1 = Ks[(kk + tg + 4) * AT_STRIDE + j * 8 + g];
                mma_tf32(s[j], a0, a1, a2, a3, b0, b1);
            }
        }
        __syncthreads();   // all reads of Ks-as-K done before P overwrite

        // scale + mask
#pragma unroll
        for (int j = 0; j < 8; ++j) {
            const int col = kt0 + j * 8 + 2 * tg;
#pragma unroll
            for (int c = 0; c < 4; ++c) {
                float sv = s[j][c] * SCALE;
                if (col + (c & 1) >= nk) sv = -1e30f;
                s[j][c] = sv;
            }
        }

        // warp-local online softmax; rows r0 = mrow+g (c0,c1), r1 = r0+8 (c2,c3)
        float m0v = -1e30f, m1v = -1e30f;
#pragma unroll
        for (int j = 0; j < 8; ++j) {
            m0v = fmaxf(m0v, fmaxf(s[j][0], s[j][1]));
            m1v = fmaxf(m1v, fmaxf(s[j][2], s[j][3]));
        }
        m0v = fmaxf(m0v, __shfl_xor_sync(0xffffffffu, m0v, 1));
        m0v = fmaxf(m0v, __shfl_xor_sync(0xffffffffu, m0v, 2));
        m1v = fmaxf(m1v, __shfl_xor_sync(0xffffffffu, m1v, 1));
        m1v = fmaxf(m1v, __shfl_xor_sync(0xffffffffu, m1v, 2));

        float nm0 = fmaxf(row_max[0], m0v);
        float nm1 = fmaxf(row_max[1], m1v);
        float corr0 = __expf(row_max[0] - nm0);
        float corr1 = __expf(row_max[1] - nm1);
        row_max[0] = nm0; row_max[1] = nm1;
        row_sum[0] *= corr0; row_sum[1] *= corr1;
#pragma unroll
        for (int j = 0; j < 8; ++j) {
            o[j][0] *= corr0; o[j][1] *= corr0;
            o[j][2] *= corr1; o[j][3] *= corr1;
        }

        uint32_t* Ps = Ks;   // reuse retired K buffer
        float ps0 = 0.f, ps1 = 0.f;
#pragma unroll
        for (int j = 0; j < 8; ++j) {
            const int col = j * 8 + 2 * tg;
            float p0 = __expf(s[j][0] - nm0);
            float p1 = __expf(s[j][1] - nm0);
            float p2 = __expf(s[j][2] - nm1);
            float p3 = __expf(s[j][3] - nm1);
            ps0 += p0 + p1; ps1 += p2 + p3;
            Ps[(mrow + g) * AT_STRIDE + col]     = f2tf32(p0);
            Ps[(mrow + g) * AT_STRIDE + col + 1] = f2tf32(p1);
            Ps[(mrow + g + 8) * AT_STRIDE + col]     = f2tf32(p2);
            Ps[(mrow + g + 8) * AT_STRIDE + col + 1] = f2tf32(p3);
        }
        ps0 += __shfl_xor_sync(0xffffffffu, ps0, 1);
        ps0 += __shfl_xor_sync(0xffffffffu, ps0, 2);
        ps1 += __shfl_xor_sync(0xffffffffu, ps1, 1);
        ps1 += __shfl_xor_sync(0xffffffffu, ps1, 2);
        row_sum[0] += ps0; row_sum[1] += ps1;
        __syncthreads();   // P fully written

        // O += P @ V : M=16 rows, N=64 (dh), K=64 (keys)
#pragma unroll
        for (int kk = 0; kk < 64; kk += 8) {
            uint32_t a0 = Ps[(mrow + g) * AT_STRIDE + kk + tg];
            uint32_t a1 = Ps[(mrow + g + 8) * AT_STRIDE + kk + tg];
            uint32_t a2 = Ps[(mrow + g) * AT_STRIDE + kk + tg + 4];
            uint32_t a3 = Ps[(mrow + g + 8) * AT_STRIDE + kk + tg + 4];
#pragma unroll
            for (int j = 0; j < 8; ++j) {
                uint32_t b0 = Vs[(kk + tg) * AT_STRIDE + j * 8 + g];
                uint32_t b1 = Vs[(kk + tg + 4) * AT_STRIDE + j * 8 + g];
                mma_tf32(o[j], a0, a1, a2, a3, b0, b1);
            }
        }
    }

    // normalize + store
    const int r0 = mrow + g, r1 = r0 + 8;
    const float inv0 = 1.f / row_sum[0];
    const float inv1 = 1.f / row_sum[1];
#pragma unroll
    for (int j = 0; j < 8; ++j) {
        const int cn = j * 8 + 2 * tg;
        if (r0 < nq)
            *(float2*)(g_att + base + (size_t)(q0 + r0) * D + cn) =
                make_float2(o[j][0] * inv0, o[j][1] * inv0);
        if (r1 < nq)
            *(float2*)(g_att + base + (size_t)(q0 + r1) * D + cn) =
                make_float2(o[j][2] * inv1, o[j][3] * inv1);
    }
}

// ---------------------------------------------------------------------------
extern "C" void kernel_launch(void* const* d_in, const int* in_sizes, int n_in,
                              void* d_out, int out_size)
{
    const float* x   = (const float*)d_in[0];
    const float* Wq  = (const float*)d_in[1];
    const float* Wk  = (const float*)d_in[2];
    const float* Wv  = (const float*)d_in[3];
    const float* Wp  = (const float*)d_in[4];
    const float* bp  = (const float*)d_in[5];
    float* out = (float*)d_out;

    cudaFuncSetAttribute(attn_kernel,
                         cudaFuncAttributeMaxDynamicSharedMemorySize, SMEM_ATTN);

    dim3 gq(D / BN, MTOT / BM, 3);           // (6, 264, 3)
    qkv_kernel<<<gq, 256>>>(x, Wq, Wk, Wv);

    dim3 ga((LSEQ + 63) / 64, NHEADS, BSZ);  // (9, 12, 64)
    attn_kernel<<<ga, 128, SMEM_ATTN>>>();

    dim3 gp(D / BN, MTOT / BM, 1);           // (6, 264)
    proj_kernel<<<gp, 256>>>(Wp, bp, out);
}

// round 4
// speedup vs baseline: 3.5138x; 1.3412x over previous
#include <cuda_runtime.h>
#include <cstdint>

#define D      768
#define LSEQ   528
#define BSZ    64
#define NHEADS 12
#define DH     64
#define MTOT   (BSZ * LSEQ)           // 33792
#define SCALE  0.03608439182435161f   // 768^-0.5
#define WELEM  (D * D)                // 589824

// Scratch (allocation-free rule: __device__ globals). All tf32-as-uint32.
__device__ uint32_t g_xt[(size_t)MTOT * D];
__device__ uint32_t g_qt[(size_t)MTOT * D];
__device__ uint32_t g_kt[(size_t)MTOT * D];
__device__ uint32_t g_vt[(size_t)MTOT * D];
__device__ uint32_t g_att[(size_t)MTOT * D];
__device__ uint32_t g_wt[4 * (size_t)WELEM];   // Wq, Wk, Wv, Wp (tf32)

__device__ __forceinline__ uint32_t f2tf32(float f) {
    uint32_t u;
    asm("cvt.rna.tf32.f32 %0, %1;" : "=r"(u) : "f"(f));
    return u;
}

__device__ __forceinline__ void mma_tf32(float c[4], uint32_t a0, uint32_t a1,
                                         uint32_t a2, uint32_t a3,
                                         uint32_t b0, uint32_t b1) {
    asm volatile(
        "mma.sync.aligned.m16n8k8.row.col.f32.tf32.tf32.f32 "
        "{%0,%1,%2,%3}, {%4,%5,%6,%7}, {%8,%9}, {%0,%1,%2,%3};"
        : "+f"(c[0]), "+f"(c[1]), "+f"(c[2]), "+f"(c[3])
        : "r"(a0), "r"(a1), "r"(a2), "r"(a3), "r"(b0), "r"(b1));
}

__device__ __forceinline__ void cp16(uint32_t smem_dst, const void* gsrc) {
    asm volatile("cp.async.cg.shared.global [%0], [%1], 16;\n"
                 :: "r"(smem_dst), "l"(gsrc));
}
#define CP_COMMIT() asm volatile("cp.async.commit_group;\n" ::: "memory")
#define CP_WAIT(N)  asm volatile("cp.async.wait_group %0;\n" :: "n"(N) : "memory")

// ---------------------------------------------------------------------------
// Pre-convert fp32 -> tf32 (vectorized)
// ---------------------------------------------------------------------------
__global__ void cvt_kernel(const float* __restrict__ in, uint32_t* __restrict__ out, int n4)
{
    int i = blockIdx.x * blockDim.x + threadIdx.x;
    if (i < n4) {
        float4 v = *(const float4*)(in + 4 * (size_t)i);
        uint4 u = make_uint4(f2tf32(v.x), f2tf32(v.y), f2tf32(v.z), f2tf32(v.w));
        *(uint4*)(out + 4 * (size_t)i) = u;
    }
}

// ---------------------------------------------------------------------------
// tf32 tensor-core GEMM: C[M,768] = A[M,768] @ W[768,768]
// 128x128 CTA tile, BK=16, 128 threads (4 warps 2x2), warp tile 64x64.
// cp.async double-buffered. A smem [m][k] stride 20; B smem [k][n] stride 132.
// OUTMODE 0: write tf32 (uint32). OUTMODE 1: write fp32 + bias.
// ---------------------------------------------------------------------------
#define BM 128
#define BN 128
#define BK 16
#define NT (D / BK)      // 48
#define ASTR 20
#define BSTR 132

template <int OUTMODE>
__device__ __forceinline__ void gemm_body(const uint32_t* __restrict__ A,
                                          const uint32_t* __restrict__ W,
                                          void* __restrict__ Cout,
                                          const float* __restrict__ bias)
{
    __shared__ uint32_t As[2][BM * ASTR];
    __shared__ uint32_t Bs[2][BK * BSTR];

    const int tid = threadIdx.x;
    const int lane = tid & 31;
    const int warp = tid >> 5;
    const int g  = lane >> 2;
    const int tg = lane & 3;
    const int mb = (warp >> 1) * 64;
    const int nb = (warp & 1) * 64;
    const int m0 = blockIdx.y * BM;
    const int n0 = blockIdx.x * BN;

    const uint32_t aSm0 = (uint32_t)__cvta_generic_to_shared(&As[0][0]);
    const uint32_t aSm1 = (uint32_t)__cvta_generic_to_shared(&As[1][0]);
    const uint32_t bSm0 = (uint32_t)__cvta_generic_to_shared(&Bs[0][0]);
    const uint32_t bSm1 = (uint32_t)__cvta_generic_to_shared(&Bs[1][0]);

    // Loader: A 128 rows x 16 cols (512 16B chunks), B 16 rows x 128 cols.
    const int a_row = tid >> 2;                 // per i: +32 rows via c
    const int b_row0 = tid >> 5;

    auto load_tiles = [&](int kt, int buf) {
        const uint32_t aS = buf ? aSm1 : aSm0;
        const uint32_t bS = buf ? bSm1 : bSm0;
#pragma unroll
        for (int i = 0; i < 4; ++i) {
            int c = tid + (i << 7);
            int row = c >> 2;
            int co = (c & 3) << 2;
            cp16(aS + (uint32_t)(row * ASTR + co) * 4,
                 A + (size_t)(m0 + row) * D + kt * BK + co);
        }
#pragma unroll
        for (int i = 0; i < 4; ++i) {
            int c = tid + (i << 7);
            int row = c >> 5;
            int col = (c & 31) << 2;
            cp16(bS + (uint32_t)(row * BSTR + col) * 4,
                 W + (size_t)(kt * BK + row) * D + n0 + col);
        }
    };

    float acc[4][8][4] = {};

    load_tiles(0, 0);
    CP_COMMIT();

    for (int kt = 0; kt < NT; ++kt) {
        const int buf = kt & 1;
        if (kt + 1 < NT) {
            load_tiles(kt + 1, buf ^ 1);
            CP_COMMIT();
            CP_WAIT(1);
        } else {
            CP_WAIT(0);
        }
        __syncthreads();

        const uint32_t* as = As[buf];
        const uint32_t* bs = Bs[buf];
#pragma unroll
        for (int kk = 0; kk < BK; kk += 8) {
            uint32_t af[4][4];
#pragma unroll
            for (int i = 0; i < 4; ++i) {
                const int r = (mb + i * 16 + g) * ASTR + kk + tg;
                af[i][0] = as[r];
                af[i][1] = as[r + 8 * ASTR];
                af[i][2] = as[r + 4];
                af[i][3] = as[r + 8 * ASTR + 4];
            }
#pragma unroll
            for (int j = 0; j < 8; ++j) {
                const uint32_t b0 = bs[(kk + tg) * BSTR + nb + j * 8 + g];
                const uint32_t b1 = bs[(kk + tg + 4) * BSTR + nb + j * 8 + g];
#pragma unroll
                for (int i = 0; i < 4; ++i)
                    mma_tf32(acc[i][j], af[i][0], af[i][1], af[i][2], af[i][3], b0, b1);
            }
        }
        __syncthreads();
    }

    // Epilogue (validated c-frag map: c0=C[g][2tg], c1=+1, c2=row+8)
#pragma unroll
    for (int j = 0; j < 8; ++j) {
        const int cn = n0 + nb + j * 8 + 2 * tg;
        float b0 = 0.f, b1 = 0.f;
        if (OUTMODE == 1) { b0 = bias[cn]; b1 = bias[cn + 1]; }
#pragma unroll
        for (int i = 0; i < 4; ++i) {
            const int rm = m0 + mb + i * 16 + g;
            if (OUTMODE == 0) {
                uint32_t* C = (uint32_t*)Cout;
                *(uint2*)(C + (size_t)rm * D + cn) =
                    make_uint2(f2tf32(acc[i][j][0]), f2tf32(acc[i][j][1]));
                *(uint2*)(C + (size_t)(rm + 8) * D + cn) =
                    make_uint2(f2tf32(acc[i][j][2]), f2tf32(acc[i][j][3]));
            } else {
                float* C = (float*)Cout;
                *(float2*)(C + (size_t)rm * D + cn) =
                    make_float2(acc[i][j][0] + b0, acc[i][j][1] + b1);
                *(float2*)(C + (size_t)(rm + 8) * D + cn) =
                    make_float2(acc[i][j][2] + b0, acc[i][j][3] + b1);
            }
        }
    }
}

__global__ void __launch_bounds__(128) qkv_kernel()
{
    const uint32_t* W = g_wt + (size_t)blockIdx.z * WELEM;
    uint32_t* C = (blockIdx.z == 0) ? g_qt : (blockIdx.z == 1) ? g_kt : g_vt;
    gemm_body<0>(g_xt, W, C, nullptr);
}

__global__ void __launch_bounds__(128) proj_kernel(const float* __restrict__ bias,
                                                   float* __restrict__ out)
{
    gemm_body<1>(g_att, g_wt + 3 * (size_t)WELEM, out, bias);
}

// ---------------------------------------------------------------------------
// tf32 tensor-core flash attention (structure validated in R2).
// Inputs already tf32 -> no conversion on loads; output written as tf32.
// ---------------------------------------------------------------------------
#define AT_STRIDE 68
#define SM_QT 0
#define SM_KS (64 * AT_STRIDE)
#define SM_VS (2 * 64 * AT_STRIDE)
#define SMEM_ATTN (3 * 64 * AT_STRIDE * 4)

__global__ void __launch_bounds__(128) attn_kernel()
{
    extern __shared__ uint32_t sm[];
    uint32_t* Qt = sm + SM_QT;
    uint32_t* Ks = sm + SM_KS;   // aliased as Ps after S phase
    uint32_t* Vs = sm + SM_VS;

    const int qt = blockIdx.x, h = blockIdx.y, b = blockIdx.z;
    const int q0 = qt << 6;
    const int nq = min(64, LSEQ - q0);
    const int nk = (q0 < 128) ? 128 : LSEQ;
    const int tid = threadIdx.x;
    const int lane = tid & 31;
    const int warp = tid >> 5;
    const int g  = lane >> 2;
    const int tg = lane & 3;
    const int mrow = warp * 16;
    const size_t base = (size_t)b * LSEQ * D + (size_t)h * DH;

#pragma unroll
    for (int it = 0; it < 8; ++it) {
        int idx = tid + (it << 7);
        int r = idx & 63;
        int c4 = (idx >> 6) << 2;
        uint4 v = make_uint4(0u, 0u, 0u, 0u);
        if (r < nq) v = *(const uint4*)(g_qt + base + (size_t)(q0 + r) * D + c4);
        Qt[(c4 + 0) * AT_STRIDE + r] = v.x;
        Qt[(c4 + 1) * AT_STRIDE + r] = v.y;
        Qt[(c4 + 2) * AT_STRIDE + r] = v.z;
        Qt[(c4 + 3) * AT_STRIDE + r] = v.w;
    }

    float o[8][4] = {};
    float row_max[2] = {-1e30f, -1e30f};
    float row_sum[2] = {0.f, 0.f};

    for (int kt0 = 0; kt0 < nk; kt0 += 64) {
        const int nkv = min(64, nk - kt0);
        __syncthreads();

#pragma unroll
        for (int it = 0; it < 8; ++it) {
            int idx = tid + (it << 7);
            int r = idx & 63;
            int c4 = (idx >> 6) << 2;
            uint4 kv = make_uint4(0u, 0u, 0u, 0u);
            if (r < nkv) kv = *(const uint4*)(g_kt + base + (size_t)(kt0 + r) * D + c4);
            Ks[(c4 + 0) * AT_STRIDE + r] = kv.x;
            Ks[(c4 + 1) * AT_STRIDE + r] = kv.y;
            Ks[(c4 + 2) * AT_STRIDE + r] = kv.z;
            Ks[(c4 + 3) * AT_STRIDE + r] = kv.w;
            int r2 = idx >> 4;
            int c2 = (idx & 15) << 2;
            uint4 vv = make_uint4(0u, 0u, 0u, 0u);
            if (r2 < nkv) vv = *(const uint4*)(g_vt + base + (size_t)(kt0 + r2) * D + c2);
            *(uint4*)&Vs[r2 * AT_STRIDE + c2] = vv;
        }
        __syncthreads();

        float s[8][4] = {};
#pragma unroll
        for (int kk = 0; kk < 64; kk += 8) {
            uint32_t a0 = Qt[(kk + tg) * AT_STRIDE + mrow + g];
            uint32_t a1 = Qt[(kk + tg) * AT_STRIDE + mrow + g + 8];
            uint32_t a2 = Qt[(kk + tg + 4) * AT_STRIDE + mrow + g];
            uint32_t a3 = Qt[(kk + tg + 4) * AT_STRIDE + mrow + g + 8];
#pragma unroll
            for (int j = 0; j < 8; ++j) {
                uint32_t b0 = Ks[(kk + tg) * AT_STRIDE + j * 8 + g];
                uint32_t b1 = Ks[(kk + tg + 4) * AT_STRIDE + j * 8 + g];
                mma_tf32(s[j], a0, a1, a2, a3, b0, b1);
            }
        }
        __syncthreads();

#pragma unroll
        for (int j = 0; j < 8; ++j) {
            const int col = kt0 + j * 8 + 2 * tg;
#pragma unroll
            for (int c = 0; c < 4; ++c) {
                float sv = s[j][c] * SCALE;
                if (col + (c & 1) >= nk) sv = -1e30f;
                s[j][c] = sv;
            }
        }

        float m0v = -1e30f, m1v = -1e30f;
#pragma unroll
        for (int j = 0; j < 8; ++j) {
            m0v = fmaxf(m0v, fmaxf(s[j][0], s[j][1]));
            m1v = fmaxf(m1v, fmaxf(s[j][2], s[j][3]));
        }
        m0v = fmaxf(m0v, __shfl_xor_sync(0xffffffffu, m0v, 1));
        m0v = fmaxf(m0v, __shfl_xor_sync(0xffffffffu, m0v, 2));
        m1v = fmaxf(m1v, __shfl_xor_sync(0xffffffffu, m1v, 1));
        m1v = fmaxf(m1v, __shfl_xor_sync(0xffffffffu, m1v, 2));

        float nm0 = fmaxf(row_max[0], m0v);
        float nm1 = fmaxf(row_max[1], m1v);
        float corr0 = __expf(row_max[0] - nm0);
        float corr1 = __expf(row_max[1] - nm1);
        row_max[0] = nm0; row_max[1] = nm1;
        row_sum[0] *= corr0; row_sum[1] *= corr1;
#pragma unroll
        for (int j = 0; j < 8; ++j) {
            o[j][0] *= corr0; o[j][1] *= corr0;
            o[j][2] *= corr1; o[j][3] *= corr1;
        }

        uint32_t* Ps = Ks;
        float ps0 = 0.f, ps1 = 0.f;
#pragma unroll
        for (int j = 0; j < 8; ++j) {
            const int col = j * 8 + 2 * tg;
            float p0 = __expf(s[j][0] - nm0);
            float p1 = __expf(s[j][1] - nm0);
            float p2 = __expf(s[j][2] - nm1);
            float p3 = __expf(s[j][3] - nm1);
            ps0 += p0 + p1; ps1 += p2 + p3;
            Ps[(mrow + g) * AT_STRIDE + col]         = f2tf32(p0);
            Ps[(mrow + g) * AT_STRIDE + col + 1]     = f2tf32(p1);
            Ps[(mrow + g + 8) * AT_STRIDE + col]     = f2tf32(p2);
            Ps[(mrow + g + 8) * AT_STRIDE + col + 1] = f2tf32(p3);
        }
        ps0 += __shfl_xor_sync(0xffffffffu, ps0, 1);
        ps0 += __shfl_xor_sync(0xffffffffu, ps0, 2);
        ps1 += __shfl_xor_sync(0xffffffffu, ps1, 1);
        ps1 += __shfl_xor_sync(0xffffffffu, ps1, 2);
        row_sum[0] += ps0; row_sum[1] += ps1;
        __syncthreads();

#pragma unroll
        for (int kk = 0; kk < 64; kk += 8) {
            uint32_t a0 = Ps[(mrow + g) * AT_STRIDE + kk + tg];
            uint32_t a1 = Ps[(mrow + g + 8) * AT_STRIDE + kk + tg];
            uint32_t a2 = Ps[(mrow + g) * AT_STRIDE + kk + tg + 4];
            uint32_t a3 = Ps[(mrow + g + 8) * AT_STRIDE + kk + tg + 4];
#pragma unroll
            for (int j = 0; j < 8; ++j) {
                uint32_t b0 = Vs[(kk + tg) * AT_STRIDE + j * 8 + g];
                uint32_t b1 = Vs[(kk + tg + 4) * AT_STRIDE + j * 8 + g];
                mma_tf32(o[j], a0, a1, a2, a3, b0, b1);
            }
        }
    }

    const int r0 = mrow + g, r1 = r0 + 8;
    const float inv0 = 1.f / row_sum[0];
    const float inv1 = 1.f / row_sum[1];
#pragma unroll
    for (int j = 0; j < 8; ++j) {
        const int cn = j * 8 + 2 * tg;
        if (r0 < nq)
            *(uint2*)(g_att + base + (size_t)(q0 + r0) * D + cn) =
                make_uint2(f2tf32(o[j][0] * inv0), f2tf32(o[j][1] * inv0));
        if (r1 < nq)
            *(uint2*)(g_att + base + (size_t)(q0 + r1) * D + cn) =
                make_uint2(f2tf32(o[j][2] * inv1), f2tf32(o[j][3] * inv1));
    }
}

// ---------------------------------------------------------------------------
extern "C" void kernel_launch(void* const* d_in, const int* in_sizes, int n_in,
                              void* d_out, int out_size)
{
    const float* x   = (const float*)d_in[0];
    const float* Wq  = (const float*)d_in[1];
    const float* Wk  = (const float*)d_in[2];
    const float* Wv  = (const float*)d_in[3];
    const float* Wp  = (const float*)d_in[4];
    const float* bp  = (const float*)d_in[5];
    float* out = (float*)d_out;

    cudaFuncSetAttribute(attn_kernel,
                         cudaFuncAttributeMaxDynamicSharedMemorySize, SMEM_ATTN);

    uint32_t* g_xt_p;  cudaGetSymbolAddress((void**)&g_xt_p, g_xt);
    uint32_t* g_wt_p;  cudaGetSymbolAddress((void**)&g_wt_p, g_wt);

    // Pre-convert inputs to tf32
    const int xn4 = (MTOT * D) / 4;         // 6488064
    const int wn4 = WELEM / 4;              // 147456
    cvt_kernel<<<(xn4 + 255) / 256, 256>>>(x, g_xt_p, xn4);
    cvt_kernel<<<(wn4 + 255) / 256, 256>>>(Wq, g_wt_p + 0 * (size_t)WELEM, wn4);
    cvt_kernel<<<(wn4 + 255) / 256, 256>>>(Wk, g_wt_p + 1 * (size_t)WELEM, wn4);
    cvt_kernel<<<(wn4 + 255) / 256, 256>>>(Wv, g_wt_p + 2 * (size_t)WELEM, wn4);
    cvt_kernel<<<(wn4 + 255) / 256, 256>>>(Wp, g_wt_p + 3 * (size_t)WELEM, wn4);

    dim3 gq(D / BN, MTOT / BM, 3);           // (6, 264, 3)
    qkv_kernel<<<gq, 128>>>();

    dim3 ga((LSEQ + 63) / 64, NHEADS, BSZ);  // (9, 12, 64)
    attn_kernel<<<ga, 128, SMEM_ATTN>>>();

    dim3 gp(D / BN, MTOT / BM, 1);           // (6, 264)
    proj_kernel<<<gp, 128>>>(bp, out);
}